// round 1
// baseline (speedup 1.0000x reference)
#include <cuda_runtime.h>
#include <cuda_fp16.h>
#include <mma.h>
#include <cstdint>

using namespace nvcuda;

#define DIM   2048
#define BB    4
#define TT    2048
#define HH    16
#define DH    128
#define BH    (BB*HH)

// ----------------------------------------------------------------------------
// Scratch (static __device__ arrays — allocation-free per harness rules)
// ----------------------------------------------------------------------------
__device__ __half g_Xh [ (size_t)BB*TT*DIM ];        // x in fp16        [8192,2048]
__device__ __half g_Wah[ (size_t)DIM*3*DIM ];        // W_attn fp16      [2048,6144]
__device__ __half g_Wph[ (size_t)DIM*DIM ];          // W_proj fp16      [2048,2048]
__device__ __half g_Q  [ (size_t)BH*TT*DH ];         // [BH, T, Dh]
__device__ __half g_K  [ (size_t)BH*TT*DH ];
__device__ __half g_V  [ (size_t)BH*TT*DH ];
__device__ __half g_Y  [ (size_t)BB*TT*DIM ];        // attention out, [B,T,C]

// ----------------------------------------------------------------------------
// float -> half convert
// ----------------------------------------------------------------------------
__global__ void f2h_kernel(const float* __restrict__ in, __half* __restrict__ out, int n) {
    int i = blockIdx.x * blockDim.x + threadIdx.x;
    int stride = gridDim.x * blockDim.x;
    for (; i < n; i += stride) out[i] = __float2half_rn(in[i]);
}

// ----------------------------------------------------------------------------
// cp.async helpers
// ----------------------------------------------------------------------------
__device__ __forceinline__ void cp16(void* smem, const void* gmem) {
    unsigned saddr = (unsigned)__cvta_generic_to_shared(smem);
    asm volatile("cp.async.cg.shared.global [%0], [%1], 16;\n" :: "r"(saddr), "l"(gmem));
}
__device__ __forceinline__ void cp_commit() {
    asm volatile("cp.async.commit_group;\n");
}
template<int N> __device__ __forceinline__ void cp_wait() {
    asm volatile("cp.async.wait_group %0;\n" :: "n"(N));
}

// ----------------------------------------------------------------------------
// Generic fp16 GEMM: C[M,N] = A[M,K] @ B[K,N] + bias
//   mode 0: scatter output (fp16) into Q/K/V [BH,T,Dh] layout (QKV gemm)
//   mode 1: write fp32 row-major to Fo (projection gemm)
// Block tile 128x128x32, 8 warps, wmma m16n16k16, cp.async double buffered.
// ----------------------------------------------------------------------------
#define BM 128
#define BN 128
#define BK 32
#define ALD (BK+8)     // 40
#define BLD (BN+8)     // 136

__global__ __launch_bounds__(256, 2)
void gemm_fp16(const __half* __restrict__ A, const __half* __restrict__ Bm,
               const float* __restrict__ bias, int K, int N, int mode,
               __half* __restrict__ Qo, __half* __restrict__ Ko,
               __half* __restrict__ Vo, float* __restrict__ Fo)
{
    __shared__ __half As[2][BM][ALD];
    __shared__ __half Bs[2][BK][BLD];
    __shared__ float  stg[8][16][20];

    const int tid  = threadIdx.x;
    const int wid  = tid >> 5;
    const int lane = tid & 31;
    const int wrow = wid >> 2;   // 0..1
    const int wcol = wid & 3;    // 0..3
    const int m0 = blockIdx.y * BM;
    const int n0 = blockIdx.x * BN;

    wmma::fragment<wmma::accumulator, 16, 16, 16, float> acc[4][2];
#pragma unroll
    for (int i = 0; i < 4; i++)
#pragma unroll
        for (int j = 0; j < 2; j++) wmma::fill_fragment(acc[i][j], 0.0f);

    const int nk = K / BK;

    // tile loaders
    auto load_tile = [&](int buf, int kt) {
        const int k0 = kt * BK;
#pragma unroll
        for (int i = tid; i < 512; i += 256) {         // A: 128 rows x 4 chunks
            int r = i >> 2, c = (i & 3) * 8;
            cp16(&As[buf][r][c], A + (size_t)(m0 + r) * K + k0 + c);
        }
#pragma unroll
        for (int i = tid; i < 512; i += 256) {         // B: 32 rows x 16 chunks
            int r = i >> 4, c = (i & 15) * 8;
            cp16(&Bs[buf][r][c], Bm + (size_t)(k0 + r) * N + n0 + c);
        }
    };

    load_tile(0, 0);
    cp_commit();

    int buf = 0;
    for (int kt = 0; kt < nk; kt++) {
        if (kt + 1 < nk) { load_tile(buf ^ 1, kt + 1); cp_commit(); cp_wait<1>(); }
        else             { cp_wait<0>(); }
        __syncthreads();

#pragma unroll
        for (int ks = 0; ks < 2; ks++) {
            wmma::fragment<wmma::matrix_a, 16, 16, 16, __half, wmma::row_major> af[4];
            wmma::fragment<wmma::matrix_b, 16, 16, 16, __half, wmma::row_major> bf[2];
#pragma unroll
            for (int i = 0; i < 4; i++)
                wmma::load_matrix_sync(af[i], &As[buf][wrow * 64 + 16 * i][ks * 16], ALD);
#pragma unroll
            for (int j = 0; j < 2; j++)
                wmma::load_matrix_sync(bf[j], &Bs[buf][ks * 16][wcol * 32 + 16 * j], BLD);
#pragma unroll
            for (int i = 0; i < 4; i++)
#pragma unroll
                for (int j = 0; j < 2; j++)
                    wmma::mma_sync(acc[i][j], af[i], bf[j], acc[i][j]);
        }
        __syncthreads();
        buf ^= 1;
    }

    // epilogue: stage each 16x16 frag through shared, add bias, write out
#pragma unroll
    for (int i = 0; i < 4; i++) {
#pragma unroll
        for (int j = 0; j < 2; j++) {
            wmma::store_matrix_sync(&stg[wid][0][0], acc[i][j], 20, wmma::mem_row_major);
            __syncwarp();
            const int mb = m0 + wrow * 64 + 16 * i;
            const int nb = n0 + wcol * 32 + 16 * j;
#pragma unroll
            for (int e = 0; e < 8; e++) {
                int idx = lane + 32 * e;               // 0..255
                int rr = idx >> 4, cc = idx & 15;
                float v = stg[wid][rr][cc] + bias[nb + cc];
                int m = mb + rr, n = nb + cc;
                if (mode == 0) {
                    int which = n >> 11;               // 0=q,1=k,2=v
                    int rem   = n & 2047;
                    int head  = rem >> 7;
                    int d     = rem & 127;
                    int b     = m >> 11;
                    int t     = m & 2047;
                    size_t dst = ((size_t)(b * HH + head) * TT + t) * DH + d;
                    __half hv = __float2half_rn(v);
                    if (which == 0)      Qo[dst] = hv;
                    else if (which == 1) Ko[dst] = hv;
                    else                 Vo[dst] = hv;
                } else {
                    Fo[(size_t)m * N + n] = v;
                }
            }
            __syncwarp();
        }
    }
}

// ----------------------------------------------------------------------------
// Flash attention: grid (T/128, BH), 256 threads (8 warps, 16 Q-rows each).
// Q tile 128 x 128, K/V tile 64 x 128. Online softmax, O accum in SMEM fp32.
// ----------------------------------------------------------------------------
#define QT  128
#define KT  64
#define QLD 136   // half ld for Qs/Ks/Vs
#define SLD 68    // float ld for S
#define PLD 72    // half ld for P
#define OLD 132   // float ld for O

#define SM_QS   0
#define SM_KS   (SM_QS + QT*QLD*2)            // 34816
#define SM_VS   (SM_KS + KT*QLD*2)            // 52224
#define SM_SS   (SM_VS + KT*QLD*2)            // 69632
#define SM_PS   (SM_SS + QT*SLD*4)            // 104448
#define SM_OS   (SM_PS + QT*PLD*2)            // 122880
#define SM_STG  (SM_OS + QT*OLD*4)            // 190464
#define SM_M    (SM_STG + 8*16*20*4)          // 200704
#define SM_L    (SM_M + QT*4)                 // 201216
#define SM_A    (SM_L + QT*4)                 // 201728
#define SMEM_FLASH (SM_A + QT*4)              // 202240

__global__ __launch_bounds__(256, 1)
void flash_kernel(const __half* __restrict__ Q, const __half* __restrict__ K,
                  const __half* __restrict__ V, __half* __restrict__ Y)
{
    extern __shared__ char sm[];
    __half* Qs  = (__half*)(sm + SM_QS);
    __half* Ks  = (__half*)(sm + SM_KS);
    __half* Vs  = (__half*)(sm + SM_VS);
    float*  Ss  = (float*) (sm + SM_SS);
    __half* Ps  = (__half*)(sm + SM_PS);
    float*  Os  = (float*) (sm + SM_OS);
    float*  stg = (float*) (sm + SM_STG);
    float*  mrow= (float*) (sm + SM_M);
    float*  lrow= (float*) (sm + SM_L);
    float*  arow= (float*) (sm + SM_A);

    const int tid  = threadIdx.x;
    const int w    = tid >> 5;
    const int lane = tid & 31;
    const int qt   = blockIdx.x;
    const int bh   = blockIdx.y;
    const int r0   = w * 16;

    const __half* Qg = Q + ((size_t)bh * TT + (size_t)qt * QT) * DH;
    const __half* Kg = K + (size_t)bh * TT * DH;
    const __half* Vg = V + (size_t)bh * TT * DH;

    // load Q tile: 128 rows x 128 halves = 2048 float4 chunks
    for (int i = tid; i < 2048; i += 256) {
        int r = i >> 4, c = (i & 15) * 8;
        *(float4*)&Qs[r * QLD + c] = *(const float4*)&Qg[(size_t)r * DH + c];
    }
    // init O, m, l
    for (int i = tid; i < QT * DH; i += 256)
        Os[(i >> 7) * OLD + (i & 127)] = 0.0f;
    if (tid < QT) { mrow[tid] = -1e30f; lrow[tid] = 0.0f; }
    __syncthreads();

    const float scale = 0.088388347648318447f;   // 1/sqrt(128)

    for (int kt = 0; kt < TT / KT; kt++) {
        // load K,V tile (64 x 128 each = 1024 float4 each)
        const __half* kg = Kg + (size_t)kt * KT * DH;
        const __half* vg = Vg + (size_t)kt * KT * DH;
        for (int i = tid; i < 1024; i += 256) {
            int r = i >> 4, c = (i & 15) * 8;
            *(float4*)&Ks[r * QLD + c] = *(const float4*)&kg[(size_t)r * DH + c];
            *(float4*)&Vs[r * QLD + c] = *(const float4*)&vg[(size_t)r * DH + c];
        }
        __syncthreads();

        // S = scale * Q K^T   (this warp's 16 rows x 64 keys)
        {
            wmma::fragment<wmma::accumulator, 16, 16, 16, float> sacc[4];
#pragma unroll
            for (int nt = 0; nt < 4; nt++) wmma::fill_fragment(sacc[nt], 0.0f);
#pragma unroll
            for (int ks = 0; ks < 8; ks++) {
                wmma::fragment<wmma::matrix_a, 16, 16, 16, __half, wmma::row_major> af;
                wmma::load_matrix_sync(af, &Qs[r0 * QLD + ks * 16], QLD);
#pragma unroll
                for (int nt = 0; nt < 4; nt++) {
                    wmma::fragment<wmma::matrix_b, 16, 16, 16, __half, wmma::col_major> bf;
                    wmma::load_matrix_sync(bf, &Ks[(nt * 16) * QLD + ks * 16], QLD);
                    wmma::mma_sync(sacc[nt], af, bf, sacc[nt]);
                }
            }
#pragma unroll
            for (int nt = 0; nt < 4; nt++) {
#pragma unroll
                for (int e = 0; e < sacc[nt].num_elements; e++) sacc[nt].x[e] *= scale;
                wmma::store_matrix_sync(&Ss[r0 * SLD + nt * 16], sacc[nt], SLD, wmma::mem_row_major);
            }
            __syncwarp();
        }

        // online softmax for this warp's rows (2 lanes per row, 32 cols each)
        {
            int r  = r0 + (lane >> 1);
            int ch = (lane & 1) * 32;
            float mx = -1e30f;
#pragma unroll
            for (int c = 0; c < 32; c++) mx = fmaxf(mx, Ss[r * SLD + ch + c]);
            mx = fmaxf(mx, __shfl_xor_sync(0xffffffff, mx, 1));
            float mprev = mrow[r];
            float mnew  = fmaxf(mprev, mx);
            float al    = __expf(mprev - mnew);
            float sum = 0.0f;
#pragma unroll
            for (int c = 0; c < 32; c++) {
                float p = __expf(Ss[r * SLD + ch + c] - mnew);
                sum += p;
                Ps[r * PLD + ch + c] = __float2half_rn(p);
            }
            sum += __shfl_xor_sync(0xffffffff, sum, 1);
            if ((lane & 1) == 0) {
                mrow[r] = mnew;
                lrow[r] = lrow[r] * al + sum;
                arow[r] = al;
            }
            __syncwarp();
            // rescale O rows by alpha
            for (int i = lane; i < 16 * DH; i += 32) {
                int rr = r0 + (i >> 7), cc = i & 127;
                Os[rr * OLD + cc] *= arow[rr];
            }
            __syncwarp();
        }

        // O += P @ V   (16 x 128 x 64)
        {
            wmma::fragment<wmma::accumulator, 16, 16, 16, float> pacc[8];
#pragma unroll
            for (int nn = 0; nn < 8; nn++) wmma::fill_fragment(pacc[nn], 0.0f);
#pragma unroll
            for (int kk = 0; kk < 4; kk++) {
                wmma::fragment<wmma::matrix_a, 16, 16, 16, __half, wmma::row_major> af;
                wmma::load_matrix_sync(af, &Ps[r0 * PLD + kk * 16], PLD);
#pragma unroll
                for (int nn = 0; nn < 8; nn++) {
                    wmma::fragment<wmma::matrix_b, 16, 16, 16, __half, wmma::row_major> bf;
                    wmma::load_matrix_sync(bf, &Vs[(kk * 16) * QLD + nn * 16], QLD);
                    wmma::mma_sync(pacc[nn], af, bf, pacc[nn]);
                }
            }
            float* st = stg + w * (16 * 20);
#pragma unroll
            for (int nn = 0; nn < 8; nn++) {
                wmma::store_matrix_sync(st, pacc[nn], 20, wmma::mem_row_major);
                __syncwarp();
#pragma unroll
                for (int e = 0; e < 8; e++) {
                    int idx = lane + 32 * e;
                    int rr = idx >> 4, cc = idx & 15;
                    Os[(r0 + rr) * OLD + nn * 16 + cc] += st[rr * 20 + cc];
                }
                __syncwarp();
            }
        }
        __syncthreads();
    }

    // normalize + write out: Y[b, t, h*Dh + d]
    const int b = bh >> 4, h = bh & 15;
    for (int i = lane; i < 16 * DH; i += 32) {
        int rr = i >> 7, cc = i & 127;
        int r  = r0 + rr;
        float v = Os[r * OLD + cc] / lrow[r];
        int t = qt * QT + r;
        Y[((size_t)(b * TT + t)) * DIM + h * DH + cc] = __float2half_rn(v);
    }
}

// ----------------------------------------------------------------------------
// launch
// ----------------------------------------------------------------------------
extern "C" void kernel_launch(void* const* d_in, const int* in_sizes, int n_in,
                              void* d_out, int out_size)
{
    const float* x      = (const float*)d_in[0];
    const float* W_attn = (const float*)d_in[1];
    const float* b_attn = (const float*)d_in[2];
    const float* W_proj = (const float*)d_in[3];
    const float* b_proj = (const float*)d_in[4];
    float* out = (float*)d_out;

    __half *Xh, *Wah, *Wph, *Qp, *Kp, *Vp, *Yp;
    cudaGetSymbolAddress((void**)&Xh,  g_Xh);
    cudaGetSymbolAddress((void**)&Wah, g_Wah);
    cudaGetSymbolAddress((void**)&Wph, g_Wph);
    cudaGetSymbolAddress((void**)&Qp,  g_Q);
    cudaGetSymbolAddress((void**)&Kp,  g_K);
    cudaGetSymbolAddress((void**)&Vp,  g_V);
    cudaGetSymbolAddress((void**)&Yp,  g_Y);

    cudaFuncSetAttribute(flash_kernel, cudaFuncAttributeMaxDynamicSharedMemorySize, SMEM_FLASH);

    const int nX  = BB * TT * DIM;      // 16,777,216
    const int nWa = DIM * 3 * DIM;      // 12,582,912
    const int nWp = DIM * DIM;          // 4,194,304

    f2h_kernel<<<4096, 256>>>(x,      Xh,  nX);
    f2h_kernel<<<4096, 256>>>(W_attn, Wah, nWa);
    f2h_kernel<<<2048, 256>>>(W_proj, Wph, nWp);

    // QKV GEMM: [8192,2048] @ [2048,6144] -> scatter to Q/K/V
    dim3 g1(3 * DIM / BN, (BB * TT) / BM);   // (48, 64)
    gemm_fp16<<<g1, 256>>>(Xh, Wah, b_attn, DIM, 3 * DIM, 0, Qp, Kp, Vp, nullptr);

    // Flash attention
    dim3 g2(TT / QT, BH);                    // (16, 64)
    flash_kernel<<<g2, 256, SMEM_FLASH>>>(Qp, Kp, Vp, Yp);

    // Projection GEMM: [8192,2048] @ [2048,2048] -> fp32 out
    dim3 g3(DIM / BN, (BB * TT) / BM);       // (16, 64)
    gemm_fp16<<<g3, 256>>>(Yp, Wph, b_proj, DIM, DIM, 1, nullptr, nullptr, nullptr, out);
}

// round 3
// speedup vs baseline: 2.2870x; 2.2870x over previous
#include <cuda_runtime.h>
#include <cuda_fp16.h>
#include <mma.h>
#include <cstdint>

using namespace nvcuda;

#define DIM   2048
#define BB    4
#define TT    2048
#define HH    16
#define DH    128
#define BH    (BB*HH)

// ----------------------------------------------------------------------------
// Scratch (static __device__ arrays — allocation-free per harness rules)
// ----------------------------------------------------------------------------
__device__ __half g_Xh [ (size_t)BB*TT*DIM ];        // x in fp16        [8192,2048]
__device__ __half g_Wah[ (size_t)DIM*3*DIM ];        // W_attn fp16      [2048,6144]
__device__ __half g_Wph[ (size_t)DIM*DIM ];          // W_proj fp16      [2048,2048]
__device__ __half g_Q  [ (size_t)BH*TT*DH ];         // [BH, T, Dh]
__device__ __half g_K  [ (size_t)BH*TT*DH ];         // [BH, T, Dh]
__device__ __half g_V  [ (size_t)BH*DH*TT ];         // V TRANSPOSED: [BH, Dh, T]
__device__ __half g_Y  [ (size_t)BB*TT*DIM ];        // attention out, [B,T,C]

// ----------------------------------------------------------------------------
// float -> half convert
// ----------------------------------------------------------------------------
__global__ void f2h_kernel(const float* __restrict__ in, __half* __restrict__ out, int n) {
    int i = blockIdx.x * blockDim.x + threadIdx.x;
    int stride = gridDim.x * blockDim.x;
    for (; i < n; i += stride) out[i] = __float2half_rn(in[i]);
}

// ----------------------------------------------------------------------------
// cp.async helpers
// ----------------------------------------------------------------------------
__device__ __forceinline__ void cp16(void* smem, const void* gmem) {
    unsigned saddr = (unsigned)__cvta_generic_to_shared(smem);
    asm volatile("cp.async.cg.shared.global [%0], [%1], 16;\n" :: "r"(saddr), "l"(gmem));
}
__device__ __forceinline__ void cp_commit() {
    asm volatile("cp.async.commit_group;\n");
}
template<int N> __device__ __forceinline__ void cp_wait() {
    asm volatile("cp.async.wait_group %0;\n" :: "n"(N));
}

// mma.sync m16n8k16 fp16 inputs, fp32 accumulate, row.col
__device__ __forceinline__ void mma16816(float* c, const uint32_t* a, uint32_t b0, uint32_t b1) {
    asm volatile(
      "mma.sync.aligned.m16n8k16.row.col.f32.f16.f16.f32 "
      "{%0,%1,%2,%3}, {%4,%5,%6,%7}, {%8,%9}, {%0,%1,%2,%3};"
      : "+f"(c[0]), "+f"(c[1]), "+f"(c[2]), "+f"(c[3])
      : "r"(a[0]), "r"(a[1]), "r"(a[2]), "r"(a[3]), "r"(b0), "r"(b1));
}

__device__ __forceinline__ uint32_t packh2(float a, float b) {
    __half2 h = __floats2half2_rn(a, b);
    return *(uint32_t*)&h;
}

// ----------------------------------------------------------------------------
// Generic fp16 GEMM: C[M,N] = A[M,K] @ B[K,N] + bias
//   mode 0: scatter fp16 output into Q/K [BH,T,Dh] and V [BH,Dh,T] (transposed)
//   mode 1: write fp32 row-major to Fo (projection gemm)
// Block tile 128x128x32, 8 warps, wmma m16n16k16, cp.async double buffered.
// ----------------------------------------------------------------------------
#define BM 128
#define BN 128
#define BK 32
#define ALD (BK+8)     // 40
#define BLD (BN+8)     // 136

__global__ __launch_bounds__(256, 2)
void gemm_fp16(const __half* __restrict__ A, const __half* __restrict__ Bm,
               const float* __restrict__ bias, int K, int N, int mode,
               __half* __restrict__ Qo, __half* __restrict__ Ko,
               __half* __restrict__ Vo, float* __restrict__ Fo)
{
    __shared__ __half As[2][BM][ALD];
    __shared__ __half Bs[2][BK][BLD];
    __shared__ float  stg[8][16][20];

    const int tid  = threadIdx.x;
    const int wid  = tid >> 5;
    const int lane = tid & 31;
    const int wrow = wid >> 2;   // 0..1
    const int wcol = wid & 3;    // 0..3
    const int m0 = blockIdx.y * BM;
    const int n0 = blockIdx.x * BN;

    wmma::fragment<wmma::accumulator, 16, 16, 16, float> acc[4][2];
#pragma unroll
    for (int i = 0; i < 4; i++)
#pragma unroll
        for (int j = 0; j < 2; j++) wmma::fill_fragment(acc[i][j], 0.0f);

    const int nk = K / BK;

    auto load_tile = [&](int buf, int kt) {
        const int k0 = kt * BK;
#pragma unroll
        for (int i = tid; i < 512; i += 256) {         // A: 128 rows x 4 chunks
            int r = i >> 2, c = (i & 3) * 8;
            cp16(&As[buf][r][c], A + (size_t)(m0 + r) * K + k0 + c);
        }
#pragma unroll
        for (int i = tid; i < 512; i += 256) {         // B: 32 rows x 16 chunks
            int r = i >> 4, c = (i & 15) * 8;
            cp16(&Bs[buf][r][c], Bm + (size_t)(k0 + r) * N + n0 + c);
        }
    };

    load_tile(0, 0);
    cp_commit();

    int buf = 0;
    for (int kt = 0; kt < nk; kt++) {
        if (kt + 1 < nk) { load_tile(buf ^ 1, kt + 1); cp_commit(); cp_wait<1>(); }
        else             { cp_wait<0>(); }
        __syncthreads();

#pragma unroll
        for (int ks = 0; ks < 2; ks++) {
            wmma::fragment<wmma::matrix_a, 16, 16, 16, __half, wmma::row_major> af[4];
            wmma::fragment<wmma::matrix_b, 16, 16, 16, __half, wmma::row_major> bf[2];
#pragma unroll
            for (int i = 0; i < 4; i++)
                wmma::load_matrix_sync(af[i], &As[buf][wrow * 64 + 16 * i][ks * 16], ALD);
#pragma unroll
            for (int j = 0; j < 2; j++)
                wmma::load_matrix_sync(bf[j], &Bs[buf][ks * 16][wcol * 32 + 16 * j], BLD);
#pragma unroll
            for (int i = 0; i < 4; i++)
#pragma unroll
                for (int j = 0; j < 2; j++)
                    wmma::mma_sync(acc[i][j], af[i], bf[j], acc[i][j]);
        }
        __syncthreads();
        buf ^= 1;
    }

    // epilogue: stage each 16x16 frag through shared, add bias, write out (16B stores)
#pragma unroll
    for (int i = 0; i < 4; i++) {
#pragma unroll
        for (int j = 0; j < 2; j++) {
            wmma::store_matrix_sync(&stg[wid][0][0], acc[i][j], 20, wmma::mem_row_major);
            __syncwarp();
            const int mb = m0 + wrow * 64 + 16 * i;
            const int nb = n0 + wcol * 32 + 16 * j;
            if (mode == 0) {
                const int which = nb >> 11;        // 0=q,1=k,2=v (frag never straddles)
                const int rem   = nb & 2047;
                const int head  = rem >> 7;
                const int d0    = rem & 127;
                const int b     = mb >> 11;
                const int tloc  = mb & 2047;
                if (which < 2) {
                    // [BH, T, Dh]: rows of frag = tokens, cols contiguous in d
                    __half* dstb = (which == 0) ? Qo : Ko;
                    const int rr  = lane & 15;
                    const int seg = lane >> 4;     // 0/1 -> col halves
                    __align__(16) __half hb[8];
#pragma unroll
                    for (int k2 = 0; k2 < 8; k2++)
                        hb[k2] = __float2half_rn(stg[wid][rr][seg * 8 + k2] + bias[nb + seg * 8 + k2]);
                    size_t dst = ((size_t)(b * HH + head) * TT + (tloc + rr)) * DH + d0 + seg * 8;
                    *(int4*)(dstb + dst) = *(const int4*)hb;
                } else {
                    // V transposed [BH, Dh, T]: cols of frag = d (rows), contiguous along t
                    const int cc  = lane & 15;
                    const int seg = lane >> 4;     // 0/1 -> row halves
                    const float bv = bias[nb + cc];
                    __align__(16) __half hb[8];
#pragma unroll
                    for (int k2 = 0; k2 < 8; k2++)
                        hb[k2] = __float2half_rn(stg[wid][seg * 8 + k2][cc] + bv);
                    size_t dst = ((size_t)(b * HH + head) * DH + d0 + cc) * TT + tloc + seg * 8;
                    *(int4*)(Vo + dst) = *(const int4*)hb;
                }
            } else {
#pragma unroll
                for (int e = 0; e < 8; e++) {
                    int idx = lane + 32 * e;
                    int rr = idx >> 4, cc = idx & 15;
                    float v = stg[wid][rr][cc] + bias[nb + cc];
                    Fo[(size_t)(mb + rr) * N + nb + cc] = v;
                }
            }
            __syncwarp();
        }
    }
}

// ----------------------------------------------------------------------------
// Flash attention v2: register-resident S/O, mma.sync m16n8k16.
// CTA = 128 threads (4 warps), Q tile 64 rows (16/warp), KV tile 64,
// cp.async double-buffered K/V. V is pre-transposed in gmem [bh][dh][t].
// ----------------------------------------------------------------------------
#define FKLD 136               // K tile: 64 rows(keys) x 128 dh, padded halves
#define FVLD 72                // Vt tile: 128 rows(dh) x 64 keys, padded halves
#define FKBYTES (64*FKLD*2)    // 17408
#define FVBYTES (128*FVLD*2)   // 18432
#define FBUF    (FKBYTES + FVBYTES)  // 35840
#define SMEM_FLASH (2*FBUF)          // 71680

__global__ __launch_bounds__(128, 2)
void flash2_kernel(const __half* __restrict__ Q, const __half* __restrict__ K,
                   const __half* __restrict__ Vt, __half* __restrict__ Y)
{
    extern __shared__ char sm[];
    const int tid  = threadIdx.x;
    const int w    = tid >> 5;
    const int lane = tid & 31;
    const int c    = lane & 3;      // threadID in group
    const int q    = lane >> 2;     // groupID
    const int qt   = blockIdx.x;    // q tile (64 rows)
    const int bh   = blockIdx.y;

    const __half* Qg  = Q  + ((size_t)bh * TT + (size_t)qt * 64) * DH;
    const __half* Kg  = K  + (size_t)bh * TT * DH;
    const __half* Vg  = Vt + (size_t)bh * DH * TT;

    auto load_kv = [&](int buf, int it) {
        __half* ks = (__half*)(sm + buf * FBUF);
        const __half* kg = Kg + (size_t)it * 64 * DH;
#pragma unroll
        for (int k = 0; k < 8; k++) {               // K: 64 rows x 16 chunks = 1024
            int i = tid + 128 * k;
            int r = i >> 4, c8 = i & 15;
            cp16(ks + r * FKLD + c8 * 8, kg + r * DH + c8 * 8);
        }
        __half* vs = (__half*)(sm + buf * FBUF + FKBYTES);
        const __half* vg = Vg + it * 64;
#pragma unroll
        for (int k = 0; k < 8; k++) {               // Vt: 128 rows x 8 chunks = 1024
            int i = tid + 128 * k;
            int r = i >> 3, c8 = i & 7;
            cp16(vs + r * FVLD + c8 * 8, vg + (size_t)r * TT + c8 * 8);
        }
    };

    // stage Q into buffer-1 K area (free until iter-1 prefetch)
    {
        __half* qs = (__half*)(sm + FBUF);
#pragma unroll
        for (int k = 0; k < 8; k++) {               // Q: 64 rows x 16 chunks = 1024
            int i = tid + 128 * k;
            int r = i >> 4, c8 = i & 15;
            cp16(qs + r * FKLD + c8 * 8, Qg + r * DH + c8 * 8);
        }
    }
    cp_commit();
    load_kv(0, 0);
    cp_commit();
    cp_wait<1>();            // Q arrived (groups retire in order)
    __syncthreads();

    // Q a-fragments: warp w owns rows w*16 .. w*16+15
    uint32_t Qa[8][4];
    {
        const uint32_t* Qs32 = (const uint32_t*)(sm + FBUF);
        const int row0 = w * 16 + q;
#pragma unroll
        for (int j = 0; j < 8; j++) {
            Qa[j][0] = Qs32[ row0      * 68 + 8 * j + c];
            Qa[j][1] = Qs32[(row0 + 8) * 68 + 8 * j + c];
            Qa[j][2] = Qs32[ row0      * 68 + 8 * j + c + 4];
            Qa[j][3] = Qs32[(row0 + 8) * 68 + 8 * j + c + 4];
        }
    }
    __syncthreads();   // everyone done reading Qs before iter-0 prefetch of buf1

    float O[16][4];
#pragma unroll
    for (int d = 0; d < 16; d++)
#pragma unroll
        for (int e = 0; e < 4; e++) O[d][e] = 0.0f;
    float mA = -1e30f, mB = -1e30f, lA = 0.0f, lB = 0.0f;

    const float scale = 0.088388347648318447f;   // 1/sqrt(128)

    for (int it = 0; it < TT / 64; it++) {
        const int buf = it & 1;
        if (it + 1 < TT / 64) { load_kv(buf ^ 1, it + 1); cp_commit(); cp_wait<1>(); }
        else                  { cp_wait<0>(); }
        __syncthreads();

        const uint32_t* Ks32 = (const uint32_t*)(sm + buf * FBUF);
        const uint32_t* Vs32 = (const uint32_t*)(sm + buf * FBUF + FKBYTES);

        // ---- S = Q K^T (16 rows x 64 keys per warp), registers ----
        float S[8][4];
#pragma unroll
        for (int n = 0; n < 8; n++)
#pragma unroll
            for (int e = 0; e < 4; e++) S[n][e] = 0.0f;

#pragma unroll
        for (int j = 0; j < 8; j++) {
#pragma unroll
            for (int n = 0; n < 8; n++) {
                uint32_t b0 = Ks32[(n * 8 + q) * 68 + 8 * j + c];
                uint32_t b1 = Ks32[(n * 8 + q) * 68 + 8 * j + c + 4];
                mma16816(S[n], Qa[j], b0, b1);
            }
        }

        // ---- online softmax (registers + quad shuffles) ----
        float rmA = -1e30f, rmB = -1e30f;
#pragma unroll
        for (int n = 0; n < 8; n++) {
#pragma unroll
            for (int e = 0; e < 4; e++) S[n][e] *= scale;
            rmA = fmaxf(rmA, fmaxf(S[n][0], S[n][1]));
            rmB = fmaxf(rmB, fmaxf(S[n][2], S[n][3]));
        }
        rmA = fmaxf(rmA, __shfl_xor_sync(0xffffffffu, rmA, 1));
        rmA = fmaxf(rmA, __shfl_xor_sync(0xffffffffu, rmA, 2));
        rmB = fmaxf(rmB, __shfl_xor_sync(0xffffffffu, rmB, 1));
        rmB = fmaxf(rmB, __shfl_xor_sync(0xffffffffu, rmB, 2));

        float mAn = fmaxf(mA, rmA);
        float mBn = fmaxf(mB, rmB);
        float aA = __expf(mA - mAn);
        float aB = __expf(mB - mBn);
        mA = mAn; mB = mBn;

        float sA = 0.0f, sB = 0.0f;
#pragma unroll
        for (int n = 0; n < 8; n++) {
            S[n][0] = __expf(S[n][0] - mA); sA += S[n][0];
            S[n][1] = __expf(S[n][1] - mA); sA += S[n][1];
            S[n][2] = __expf(S[n][2] - mB); sB += S[n][2];
            S[n][3] = __expf(S[n][3] - mB); sB += S[n][3];
        }
        sA += __shfl_xor_sync(0xffffffffu, sA, 1);
        sA += __shfl_xor_sync(0xffffffffu, sA, 2);
        sB += __shfl_xor_sync(0xffffffffu, sB, 1);
        sB += __shfl_xor_sync(0xffffffffu, sB, 2);
        lA = lA * aA + sA;
        lB = lB * aB + sB;

#pragma unroll
        for (int d = 0; d < 16; d++) {
            O[d][0] *= aA; O[d][1] *= aA;
            O[d][2] *= aB; O[d][3] *= aB;
        }

        // ---- O += P @ V : P a-frags come straight from S registers ----
#pragma unroll
        for (int jk = 0; jk < 4; jk++) {
            uint32_t pa[4];
            pa[0] = packh2(S[2 * jk][0],     S[2 * jk][1]);
            pa[1] = packh2(S[2 * jk][2],     S[2 * jk][3]);
            pa[2] = packh2(S[2 * jk + 1][0], S[2 * jk + 1][1]);
            pa[3] = packh2(S[2 * jk + 1][2], S[2 * jk + 1][3]);
#pragma unroll
            for (int d = 0; d < 16; d++) {
                uint32_t b0 = Vs32[(8 * d + q) * 36 + 8 * jk + c];
                uint32_t b1 = Vs32[(8 * d + q) * 36 + 8 * jk + c + 4];
                mma16816(O[d], pa, b0, b1);
            }
        }
        __syncthreads();   // done reading buf before it is overwritten next iter
    }

    // ---- epilogue: normalize + write Y[b, t, h*Dh + d] as half2 ----
    const int b = bh >> 4, h = bh & 15;
    const int tok0 = qt * 64 + w * 16 + q;
    const float iA = 1.0f / lA;
    const float iB = 1.0f / lB;
    __half* Y0 = Y + ((size_t)b * TT + tok0)     * DIM + h * DH;
    __half* Y1 = Y + ((size_t)b * TT + tok0 + 8) * DIM + h * DH;
#pragma unroll
    for (int d = 0; d < 16; d++) {
        __half2 v0 = __floats2half2_rn(O[d][0] * iA, O[d][1] * iA);
        __half2 v1 = __floats2half2_rn(O[d][2] * iB, O[d][3] * iB);
        *(__half2*)(Y0 + d * 8 + 2 * c) = v0;
        *(__half2*)(Y1 + d * 8 + 2 * c) = v1;
    }
}

// ----------------------------------------------------------------------------
// launch
// ----------------------------------------------------------------------------
extern "C" void kernel_launch(void* const* d_in, const int* in_sizes, int n_in,
                              void* d_out, int out_size)
{
    const float* x      = (const float*)d_in[0];
    const float* W_attn = (const float*)d_in[1];
    const float* b_attn = (const float*)d_in[2];
    const float* W_proj = (const float*)d_in[3];
    const float* b_proj = (const float*)d_in[4];
    float* out = (float*)d_out;

    __half *Xh, *Wah, *Wph, *Qp, *Kp, *Vp, *Yp;
    cudaGetSymbolAddress((void**)&Xh,  g_Xh);
    cudaGetSymbolAddress((void**)&Wah, g_Wah);
    cudaGetSymbolAddress((void**)&Wph, g_Wph);
    cudaGetSymbolAddress((void**)&Qp,  g_Q);
    cudaGetSymbolAddress((void**)&Kp,  g_K);
    cudaGetSymbolAddress((void**)&Vp,  g_V);
    cudaGetSymbolAddress((void**)&Yp,  g_Y);

    cudaFuncSetAttribute(flash2_kernel, cudaFuncAttributeMaxDynamicSharedMemorySize, SMEM_FLASH);

    const int nX  = BB * TT * DIM;      // 16,777,216
    const int nWa = DIM * 3 * DIM;      // 12,582,912
    const int nWp = DIM * DIM;          // 4,194,304

    f2h_kernel<<<4096, 256>>>(x,      Xh,  nX);
    f2h_kernel<<<4096, 256>>>(W_attn, Wah, nWa);
    f2h_kernel<<<2048, 256>>>(W_proj, Wph, nWp);

    // QKV GEMM: [8192,2048] @ [2048,6144] -> scatter to Q/K (tokens-major) and V^T
    dim3 g1(3 * DIM / BN, (BB * TT) / BM);   // (48, 64)
    gemm_fp16<<<g1, 256>>>(Xh, Wah, b_attn, DIM, 3 * DIM, 0, Qp, Kp, Vp, nullptr);

    // Flash attention v2
    dim3 g2(TT / 64, BH);                    // (32, 64)
    flash2_kernel<<<g2, 128, SMEM_FLASH>>>(Qp, Kp, Vp, Yp);

    // Projection GEMM: [8192,2048] @ [2048,2048] -> fp32 out
    dim3 g3(DIM / BN, (BB * TT) / BM);       // (16, 64)
    gemm_fp16<<<g3, 256>>>(Yp, Wph, b_proj, DIM, DIM, 1, nullptr, nullptr, nullptr, out);
}

// round 5
// speedup vs baseline: 2.4065x; 1.0522x over previous
#include <cuda_runtime.h>
#include <cuda_fp16.h>
#include <cstdint>

#define DIM   2048
#define BB    4
#define TT    2048
#define HH    16
#define DH    128
#define BH    (BB*HH)
#define GK    2048

// ----------------------------------------------------------------------------
// Scratch
// ----------------------------------------------------------------------------
__device__ __half g_Xh [ (size_t)BB*TT*DIM ];        // x fp16 [8192,2048]
__device__ __half g_Wat[ (size_t)3*DIM*DIM ];        // W_attn^T fp16 [6144,2048]
__device__ __half g_Wpt[ (size_t)DIM*DIM ];          // W_proj^T fp16 [2048,2048]
__device__ __half g_Q  [ (size_t)BH*TT*DH ];         // [BH, T, Dh]
__device__ __half g_K  [ (size_t)BH*TT*DH ];         // [BH, T, Dh]
__device__ __half g_V  [ (size_t)BH*DH*TT ];         // V^T: [BH, Dh, T]
__device__ __half g_Y  [ (size_t)BB*TT*DIM ];        // attention out [B,T,C]

// ----------------------------------------------------------------------------
// converts
// ----------------------------------------------------------------------------
__global__ void f2h8_kernel(const float4* __restrict__ in, int4* __restrict__ out, int n8) {
    int i = blockIdx.x * blockDim.x + threadIdx.x;
    if (i >= n8) return;
    float4 x0 = in[2 * i], x1 = in[2 * i + 1];
    __half2 h[4];
    h[0] = __floats2half2_rn(x0.x, x0.y);
    h[1] = __floats2half2_rn(x0.z, x0.w);
    h[2] = __floats2half2_rn(x1.x, x1.y);
    h[3] = __floats2half2_rn(x1.z, x1.w);
    out[i] = *(const int4*)h;
}

// in[R][C] f32 -> out[C][R] f16
__global__ void transpose_f2h(const float* __restrict__ in, __half* __restrict__ out,
                              int R, int C) {
    __shared__ float t[32][33];
    int c0 = blockIdx.x * 32, r0 = blockIdx.y * 32;
    int x = threadIdx.x, y = threadIdx.y;   // block (32,8)
#pragma unroll
    for (int j = 0; j < 32; j += 8) t[y + j][x] = in[(size_t)(r0 + y + j) * C + c0 + x];
    __syncthreads();
#pragma unroll
    for (int j = 0; j < 32; j += 8)
        out[(size_t)(c0 + y + j) * R + r0 + x] = __float2half_rn(t[x][y + j]);
}

// ----------------------------------------------------------------------------
// cp.async + mma helpers
// ----------------------------------------------------------------------------
__device__ __forceinline__ void cp16(void* smem, const void* gmem) {
    unsigned saddr = (unsigned)__cvta_generic_to_shared(smem);
    asm volatile("cp.async.cg.shared.global [%0], [%1], 16;\n" :: "r"(saddr), "l"(gmem));
}
__device__ __forceinline__ void cp_commit() { asm volatile("cp.async.commit_group;\n"); }
template<int N> __device__ __forceinline__ void cp_wait() {
    asm volatile("cp.async.wait_group %0;\n" :: "n"(N));
}

__device__ __forceinline__ void mma16816(float* c, const uint32_t* a, uint32_t b0, uint32_t b1) {
    asm volatile(
      "mma.sync.aligned.m16n8k16.row.col.f32.f16.f16.f32 "
      "{%0,%1,%2,%3}, {%4,%5,%6,%7}, {%8,%9}, {%0,%1,%2,%3};"
      : "+f"(c[0]), "+f"(c[1]), "+f"(c[2]), "+f"(c[3])
      : "r"(a[0]), "r"(a[1]), "r"(a[2]), "r"(a[3]), "r"(b0), "r"(b1));
}
__device__ __forceinline__ uint32_t packh2(float a, float b) {
    __half2 h = __floats2half2_rn(a, b);
    return *(uint32_t*)&h;
}

// ----------------------------------------------------------------------------
// mma.sync GEMM: C[8192, N] = A[8192,2048] @ Bt[N,2048]^T + bias
//   mode 0: N=6144, scatter fp16 to Q/K [BH,T,Dh] and V^T [BH,Dh,T]
//   mode 1: N=2048, fp32 row-major to Fo
// CTA 128x256, BK=64 halves (128B rows, XOR-16B swizzle), 8 warps, warp 64x64.
// 4-stage cp.async pipeline.
// ----------------------------------------------------------------------------
#define GSTG_A   16384                      // 128 rows * 128B
#define GSTG_B   32768                      // 256 rows * 128B
#define GSTG     (GSTG_A + GSTG_B)          // 49152
#define NSTAGE   4
#define NKS      32                         // 2048 / 64
#define SMEM_GEMM (NSTAGE * GSTG)           // 196608

// word layout within a 128B row: phys word = (w&3) + 4*((w>>2) ^ (r&7))
__device__ __forceinline__ int swz_w(int r, int w) {
    return (w & 3) + 4 * (((w >> 2) ^ r) & 7);
}

__global__ __launch_bounds__(256, 1)
void gemm_mma(const __half* __restrict__ A, const __half* __restrict__ Bt,
              const float* __restrict__ bias, int mode,
              __half* __restrict__ Qo, __half* __restrict__ Ko,
              __half* __restrict__ Vo, float* __restrict__ Fo)
{
    extern __shared__ char sm[];
    const int tid  = threadIdx.x;
    const int wid  = tid >> 5;
    const int lane = tid & 31;
    const int c    = lane & 3;
    const int q    = lane >> 2;
    const int wm   = wid >> 2;          // 0..1
    const int wn   = wid & 3;           // 0..3
    const int m0   = blockIdx.y * 128;
    const int n0   = blockIdx.x * 256;

    const __half* Ag = A  + (size_t)m0 * GK;
    const __half* Bg = Bt + (size_t)n0 * GK;

    auto load_stage = [&](int s, int kt) {
        char* ab = sm + s * GSTG;
        const __half* ag = Ag + kt * 64;
#pragma unroll
        for (int it = 0; it < 4; it++) {              // A: 1024 chunks of 16B
            int i = tid + 256 * it;
            int r = i >> 3, c16 = i & 7;
            cp16(ab + r * 128 + 16 * ((c16 ^ r) & 7), ag + (size_t)r * GK + c16 * 8);
        }
        char* bb = ab + GSTG_A;
        const __half* bg = Bg + kt * 64;
#pragma unroll
        for (int it = 0; it < 8; it++) {              // B: 2048 chunks of 16B
            int i = tid + 256 * it;
            int r = i >> 3, c16 = i & 7;
            cp16(bb + r * 128 + 16 * ((c16 ^ r) & 7), bg + (size_t)r * GK + c16 * 8);
        }
    };

    load_stage(0, 0); cp_commit();
    load_stage(1, 1); cp_commit();
    load_stage(2, 2); cp_commit();

    float acc[4][8][4];
#pragma unroll
    for (int mi = 0; mi < 4; mi++)
#pragma unroll
        for (int ni = 0; ni < 8; ni++)
#pragma unroll
            for (int e = 0; e < 4; e++) acc[mi][ni][e] = 0.0f;

    for (int kt = 0; kt < NKS; kt++) {
        if      (kt <= NKS - 3) cp_wait<2>();
        else if (kt == NKS - 2) cp_wait<1>();
        else                    cp_wait<0>();
        __syncthreads();
        if (kt + 3 < NKS) { load_stage((kt + 3) & 3, kt + 3); cp_commit(); }

        const uint32_t* As32 = (const uint32_t*)(sm + (kt & 3) * GSTG);
        const uint32_t* Bs32 = (const uint32_t*)(sm + (kt & 3) * GSTG + GSTG_A);

#pragma unroll
        for (int j = 0; j < 4; j++) {
            uint32_t Af[4][4];
#pragma unroll
            for (int mi = 0; mi < 4; mi++) {
                const int ra = wm * 64 + 16 * mi + q;
                Af[mi][0] = As32[ ra      * 32 + swz_w(ra, 8 * j + c)];
                Af[mi][1] = As32[(ra + 8) * 32 + swz_w(ra, 8 * j + c)];
                Af[mi][2] = As32[ ra      * 32 + swz_w(ra, 8 * j + c + 4)];
                Af[mi][3] = As32[(ra + 8) * 32 + swz_w(ra, 8 * j + c + 4)];
            }
            uint32_t Bf[8][2];
#pragma unroll
            for (int ni = 0; ni < 8; ni++) {
                const int rb = wn * 64 + 8 * ni + q;
                Bf[ni][0] = Bs32[rb * 32 + swz_w(rb, 8 * j + c)];
                Bf[ni][1] = Bs32[rb * 32 + swz_w(rb, 8 * j + c + 4)];
            }
#pragma unroll
            for (int mi = 0; mi < 4; mi++)
#pragma unroll
                for (int ni = 0; ni < 8; ni++)
                    mma16816(acc[mi][ni], Af[mi], Bf[ni][0], Bf[ni][1]);
        }
    }

    // ---- epilogue: straight from registers ----
    const int n_w = n0 + 64 * wn;
    if (mode == 0) {
        const int region = n_w >> 11;          // 0=q,1=k,2=v (64-tile never straddles)
        const int rem    = n_w & 2047;
        const int head   = rem >> 7;
        const int d_base = rem & 127;          // 0 or 64
        const int b      = m0 >> 11;
        const int bh     = b * HH + head;
        const int tbase  = (m0 & 2047) + 64 * wm;
        if (region < 2) {
            __half* dstb = (region == 0) ? Qo : Ko;
#pragma unroll
            for (int ni = 0; ni < 8; ni++) {
                const int d = d_base + 8 * ni + 2 * c;
                const float2 bv = *(const float2*)(bias + n_w + 8 * ni + 2 * c);
#pragma unroll
                for (int mi = 0; mi < 4; mi++) {
                    const int t0 = tbase + 16 * mi + q;
                    *(uint32_t*)(dstb + ((size_t)bh * TT + t0)     * DH + d) =
                        packh2(acc[mi][ni][0] + bv.x, acc[mi][ni][1] + bv.y);
                    *(uint32_t*)(dstb + ((size_t)bh * TT + t0 + 8) * DH + d) =
                        packh2(acc[mi][ni][2] + bv.x, acc[mi][ni][3] + bv.y);
                }
            }
        } else {
#pragma unroll
            for (int ni = 0; ni < 8; ni++) {
                const int d = d_base + 8 * ni + 2 * c;
                const float2 bv = *(const float2*)(bias + n_w + 8 * ni + 2 * c);
                __half* p0 = Vo + ((size_t)bh * DH + d)     * TT;
                __half* p1 = Vo + ((size_t)bh * DH + d + 1) * TT;
#pragma unroll
                for (int mi = 0; mi < 4; mi++) {
                    const int t0 = tbase + 16 * mi + q;
                    p0[t0]     = __float2half_rn(acc[mi][ni][0] + bv.x);
                    p1[t0]     = __float2half_rn(acc[mi][ni][1] + bv.y);
                    p0[t0 + 8] = __float2half_rn(acc[mi][ni][2] + bv.x);
                    p1[t0 + 8] = __float2half_rn(acc[mi][ni][3] + bv.y);
                }
            }
        }
    } else {
        const int mbase = m0 + 64 * wm;
#pragma unroll
        for (int ni = 0; ni < 8; ni++) {
            const int col = n_w + 8 * ni + 2 * c;
            const float2 bv = *(const float2*)(bias + col);
#pragma unroll
            for (int mi = 0; mi < 4; mi++) {
                const int mr = mbase + 16 * mi + q;
                float2 v0 = {acc[mi][ni][0] + bv.x, acc[mi][ni][1] + bv.y};
                float2 v1 = {acc[mi][ni][2] + bv.x, acc[mi][ni][3] + bv.y};
                *(float2*)(Fo + (size_t)mr * DIM + col)       = v0;
                *(float2*)(Fo + (size_t)(mr + 8) * DIM + col) = v1;
            }
        }
    }
}

// ----------------------------------------------------------------------------
// Flash attention v2 (unchanged, passing)
// ----------------------------------------------------------------------------
#define FKLD 136
#define FVLD 72
#define FKBYTES (64*FKLD*2)
#define FVBYTES (128*FVLD*2)
#define FBUF    (FKBYTES + FVBYTES)
#define SMEM_FLASH (2*FBUF)

__global__ __launch_bounds__(128, 2)
void flash2_kernel(const __half* __restrict__ Q, const __half* __restrict__ K,
                   const __half* __restrict__ Vt, __half* __restrict__ Y)
{
    extern __shared__ char sm[];
    const int tid  = threadIdx.x;
    const int w    = tid >> 5;
    const int lane = tid & 31;
    const int c    = lane & 3;
    const int q    = lane >> 2;
    const int qt   = blockIdx.x;
    const int bh   = blockIdx.y;

    const __half* Qg  = Q  + ((size_t)bh * TT + (size_t)qt * 64) * DH;
    const __half* Kg  = K  + (size_t)bh * TT * DH;
    const __half* Vg  = Vt + (size_t)bh * DH * TT;

    auto load_kv = [&](int buf, int it) {
        __half* ks = (__half*)(sm + buf * FBUF);
        const __half* kg = Kg + (size_t)it * 64 * DH;
#pragma unroll
        for (int k = 0; k < 8; k++) {
            int i = tid + 128 * k;
            int r = i >> 4, c8 = i & 15;
            cp16(ks + r * FKLD + c8 * 8, kg + r * DH + c8 * 8);
        }
        __half* vs = (__half*)(sm + buf * FBUF + FKBYTES);
        const __half* vg = Vg + it * 64;
#pragma unroll
        for (int k = 0; k < 8; k++) {
            int i = tid + 128 * k;
            int r = i >> 3, c8 = i & 7;
            cp16(vs + r * FVLD + c8 * 8, vg + (size_t)r * TT + c8 * 8);
        }
    };

    {
        __half* qs = (__half*)(sm + FBUF);
#pragma unroll
        for (int k = 0; k < 8; k++) {
            int i = tid + 128 * k;
            int r = i >> 4, c8 = i & 15;
            cp16(qs + r * FKLD + c8 * 8, Qg + r * DH + c8 * 8);
        }
    }
    cp_commit();
    load_kv(0, 0);
    cp_commit();
    cp_wait<1>();
    __syncthreads();

    uint32_t Qa[8][4];
    {
        const uint32_t* Qs32 = (const uint32_t*)(sm + FBUF);
        const int row0 = w * 16 + q;
#pragma unroll
        for (int j = 0; j < 8; j++) {
            Qa[j][0] = Qs32[ row0      * 68 + 8 * j + c];
            Qa[j][1] = Qs32[(row0 + 8) * 68 + 8 * j + c];
            Qa[j][2] = Qs32[ row0      * 68 + 8 * j + c + 4];
            Qa[j][3] = Qs32[(row0 + 8) * 68 + 8 * j + c + 4];
        }
    }
    __syncthreads();

    float O[16][4];
#pragma unroll
    for (int d = 0; d < 16; d++)
#pragma unroll
        for (int e = 0; e < 4; e++) O[d][e] = 0.0f;
    float mA = -1e30f, mB = -1e30f, lA = 0.0f, lB = 0.0f;

    const float scale = 0.088388347648318447f;

    for (int it = 0; it < TT / 64; it++) {
        const int buf = it & 1;
        if (it + 1 < TT / 64) { load_kv(buf ^ 1, it + 1); cp_commit(); cp_wait<1>(); }
        else                  { cp_wait<0>(); }
        __syncthreads();

        const uint32_t* Ks32 = (const uint32_t*)(sm + buf * FBUF);
        const uint32_t* Vs32 = (const uint32_t*)(sm + buf * FBUF + FKBYTES);

        float S[8][4];
#pragma unroll
        for (int n = 0; n < 8; n++)
#pragma unroll
            for (int e = 0; e < 4; e++) S[n][e] = 0.0f;

#pragma unroll
        for (int j = 0; j < 8; j++) {
#pragma unroll
            for (int n = 0; n < 8; n++) {
                uint32_t b0 = Ks32[(n * 8 + q) * 68 + 8 * j + c];
                uint32_t b1 = Ks32[(n * 8 + q) * 68 + 8 * j + c + 4];
                mma16816(S[n], Qa[j], b0, b1);
            }
        }

        float rmA = -1e30f, rmB = -1e30f;
#pragma unroll
        for (int n = 0; n < 8; n++) {
#pragma unroll
            for (int e = 0; e < 4; e++) S[n][e] *= scale;
            rmA = fmaxf(rmA, fmaxf(S[n][0], S[n][1]));
            rmB = fmaxf(rmB, fmaxf(S[n][2], S[n][3]));
        }
        rmA = fmaxf(rmA, __shfl_xor_sync(0xffffffffu, rmA, 1));
        rmA = fmaxf(rmA, __shfl_xor_sync(0xffffffffu, rmA, 2));
        rmB = fmaxf(rmB, __shfl_xor_sync(0xffffffffu, rmB, 1));
        rmB = fmaxf(rmB, __shfl_xor_sync(0xffffffffu, rmB, 2));

        float mAn = fmaxf(mA, rmA);
        float mBn = fmaxf(mB, rmB);
        float aA = __expf(mA - mAn);
        float aB = __expf(mB - mBn);
        mA = mAn; mB = mBn;

        float sA = 0.0f, sB = 0.0f;
#pragma unroll
        for (int n = 0; n < 8; n++) {
            S[n][0] = __expf(S[n][0] - mA); sA += S[n][0];
            S[n][1] = __expf(S[n][1] - mA); sA += S[n][1];
            S[n][2] = __expf(S[n][2] - mB); sB += S[n][2];
            S[n][3] = __expf(S[n][3] - mB); sB += S[n][3];
        }
        sA += __shfl_xor_sync(0xffffffffu, sA, 1);
        sA += __shfl_xor_sync(0xffffffffu, sA, 2);
        sB += __shfl_xor_sync(0xffffffffu, sB, 1);
        sB += __shfl_xor_sync(0xffffffffu, sB, 2);
        lA = lA * aA + sA;
        lB = lB * aB + sB;

#pragma unroll
        for (int d = 0; d < 16; d++) {
            O[d][0] *= aA; O[d][1] *= aA;
            O[d][2] *= aB; O[d][3] *= aB;
        }

#pragma unroll
        for (int jk = 0; jk < 4; jk++) {
            uint32_t pa[4];
            pa[0] = packh2(S[2 * jk][0],     S[2 * jk][1]);
            pa[1] = packh2(S[2 * jk][2],     S[2 * jk][3]);
            pa[2] = packh2(S[2 * jk + 1][0], S[2 * jk + 1][1]);
            pa[3] = packh2(S[2 * jk + 1][2], S[2 * jk + 1][3]);
#pragma unroll
            for (int d = 0; d < 16; d++) {
                uint32_t b0 = Vs32[(8 * d + q) * 36 + 8 * jk + c];
                uint32_t b1 = Vs32[(8 * d + q) * 36 + 8 * jk + c + 4];
                mma16816(O[d], pa, b0, b1);
            }
        }
        __syncthreads();
    }

    const int b = bh >> 4, h = bh & 15;
    const int tok0 = qt * 64 + w * 16 + q;
    const float iA = 1.0f / lA;
    const float iB = 1.0f / lB;
    __half* Y0 = Y + ((size_t)b * TT + tok0)     * DIM + h * DH;
    __half* Y1 = Y + ((size_t)b * TT + tok0 + 8) * DIM + h * DH;
#pragma unroll
    for (int d = 0; d < 16; d++) {
        __half2 v0 = __floats2half2_rn(O[d][0] * iA, O[d][1] * iA);
        __half2 v1 = __floats2half2_rn(O[d][2] * iB, O[d][3] * iB);
        *(__half2*)(Y0 + d * 8 + 2 * c) = v0;
        *(__half2*)(Y1 + d * 8 + 2 * c) = v1;
    }
}

// ----------------------------------------------------------------------------
// launch
// ----------------------------------------------------------------------------
extern "C" void kernel_launch(void* const* d_in, const int* in_sizes, int n_in,
                              void* d_out, int out_size)
{
    const float* x      = (const float*)d_in[0];
    const float* W_attn = (const float*)d_in[1];
    const float* b_attn = (const float*)d_in[2];
    const float* W_proj = (const float*)d_in[3];
    const float* b_proj = (const float*)d_in[4];
    float* out = (float*)d_out;

    __half *Xh, *Wat, *Wpt, *Qp, *Kp, *Vp, *Yp;
    cudaGetSymbolAddress((void**)&Xh,  g_Xh);
    cudaGetSymbolAddress((void**)&Wat, g_Wat);
    cudaGetSymbolAddress((void**)&Wpt, g_Wpt);
    cudaGetSymbolAddress((void**)&Qp,  g_Q);
    cudaGetSymbolAddress((void**)&Kp,  g_K);
    cudaGetSymbolAddress((void**)&Vp,  g_V);
    cudaGetSymbolAddress((void**)&Yp,  g_Y);

    cudaFuncSetAttribute(gemm_mma, cudaFuncAttributeMaxDynamicSharedMemorySize, SMEM_GEMM);
    cudaFuncSetAttribute(flash2_kernel, cudaFuncAttributeMaxDynamicSharedMemorySize, SMEM_FLASH);

    const int nX8 = BB * TT * DIM / 8;   // 2,097,152

    f2h8_kernel<<<(nX8 + 255) / 256, 256>>>((const float4*)x, (int4*)Xh, nX8);
    transpose_f2h<<<dim3(3 * DIM / 32, DIM / 32), dim3(32, 8)>>>(W_attn, Wat, DIM, 3 * DIM);
    transpose_f2h<<<dim3(DIM / 32, DIM / 32),     dim3(32, 8)>>>(W_proj, Wpt, DIM, DIM);

    // QKV GEMM: scatter to Q/K and V^T
    dim3 g1(3 * DIM / 256, (BB * TT) / 128);   // (24, 64)
    gemm_mma<<<g1, 256, SMEM_GEMM>>>(Xh, Wat, b_attn, 0, Qp, Kp, Vp, nullptr);

    // Flash attention
    dim3 g2(TT / 64, BH);                      // (32, 64)
    flash2_kernel<<<g2, 128, SMEM_FLASH>>>(Qp, Kp, Vp, Yp);

    // Projection GEMM: fp32 out
    dim3 g3(DIM / 256, (BB * TT) / 128);       // (8, 64)
    gemm_mma<<<g3, 256, SMEM_GEMM>>>(Yp, Wpt, b_proj, 1, nullptr, nullptr, nullptr, out);
}